// round 3
// baseline (speedup 1.0000x reference)
#include <cuda_runtime.h>
#include <math.h>

// ---------------------------------------------------------------------------
// SLAYER N-MNIST SNN forward, fused pipeline (6 launches):
//   conv1+spike -> pool+spike -> conv2+spike -> pool+spike -> conv3+spike
//   -> fc+spike(out)
// Layout everywhere: [B, C, H, W, T], T=300 innermost (matches reference).
// All intermediates hold SPIKES (0/1 floats); membrane potentials never
// leave shared memory.
// ---------------------------------------------------------------------------

#define T_LEN   300
#define BATCH   8
#define THETA   10.0f

// Scratch spike tensors (static device arrays; no allocation anywhere)
__device__ float g_s1[BATCH * 16 * 32 * 32 * T_LEN];
__device__ float g_s2[BATCH * 16 * 16 * 16 * T_LEN];
__device__ float g_s3[BATCH * 32 * 16 * 16 * T_LEN];
__device__ float g_s4[BATCH * 32 *  8 *  8 * T_LEN];
__device__ float g_s5[BATCH * 64 *  8 *  8 * T_LEN];

// Refractory taps REF_KERNEL[1..10] = -20 * j * exp(1 - j), computed in
// double then cast to f32 (bit-matches the numpy host computation).
__device__ __forceinline__ void load_refk(float rk[10]) {
    #pragma unroll
    for (int j = 0; j < 10; j++)
        rk[j] = (float)(-20.0 * (double)(j + 1) * exp(1.0 - (double)(j + 1)));
}

// One step of the spike recurrence. Matches jax.lax.scan step exactly:
// buf_new[j] = buf_old[j+1] + ev*refk[j]  (ev in {0,1} => ev*rk exact,
// so fmaf == single-rounded add, same as the reference).
__device__ __forceinline__ float spike_step(float u_raw, float buf[10],
                                            const float rk[10]) {
    const float um = u_raw + buf[0];
    const float ev = (um >= THETA) ? 1.0f : 0.0f;
    #pragma unroll
    for (int j = 0; j < 9; j++)
        buf[j] = fmaf(ev, rk[j], buf[j + 1]);
    buf[9] = ev * rk[9];
    return ev;   // amplitude 1/Ts, Ts = 1
}

// ---------------------------------------------------------------------------
// Fused conv + spike.
// Block = one (b, y, x) for OT output channels, threads tile t as float2.
// Membrane potentials live in smem su[OT][301] (stride 301: the OT=16
// recurrence threads map to 16 distinct banks since 16*13 mod 32 are all
// distinct); spikes are written back coalesced.
// ---------------------------------------------------------------------------
template<int C, int O, int K, int PAD, int HIN, int WIN, int HOUT, int WOUT, int OT>
__global__ __launch_bounds__(128)
void conv_spike_kernel(const float* __restrict__ in, const float* __restrict__ wt,
                       float* __restrict__ out)
{
    constexpr int KK = K * K;
    constexpr int SUP = 301;          // padded row stride (odd -> conflict-free)
    __shared__ float sw[C * KK * OT];
    __shared__ float su[OT][SUP];

    const int tid = threadIdx.x;
    const int o0  = blockIdx.z * OT;

    // Stage weights transposed: sw[j*OT + ot] = wt[(o0+ot)*C*KK + j]
    for (int i = tid; i < C * KK * OT; i += 128) {
        int ot = i % OT;
        int j  = i / OT;
        sw[j * OT + ot] = wt[(size_t)(o0 + ot) * C * KK + j];
    }
    __syncthreads();

    const int y = blockIdx.x / WOUT;
    const int x = blockIdx.x % WOUT;
    const int b = blockIdx.y;

    // ---- conv phase: accumulate membrane potential into su ----
    for (int tp = tid; tp < T_LEN / 2; tp += 128) {
        float2 acc[OT];
        #pragma unroll
        for (int ot = 0; ot < OT; ot++) { acc[ot].x = 0.f; acc[ot].y = 0.f; }

        #pragma unroll 1
        for (int c = 0; c < C; c++) {
            #pragma unroll
            for (int dy = 0; dy < K; dy++) {
                const int iy = y + dy - PAD;
                if (iy < 0 || iy >= HIN) continue;
                #pragma unroll
                for (int dx = 0; dx < K; dx++) {
                    const int ix = x + dx - PAD;
                    if (ix < 0 || ix >= WIN) continue;
                    const size_t ib =
                        ((size_t)(((b * C + c) * HIN + iy) * WIN + ix)) * T_LEN + 2 * tp;
                    const float2 v = *reinterpret_cast<const float2*>(&in[ib]);
                    const float4* wrow =
                        reinterpret_cast<const float4*>(&sw[(c * KK + dy * K + dx) * OT]);
                    #pragma unroll
                    for (int q = 0; q < OT / 4; q++) {
                        const float4 w4 = wrow[q];
                        acc[4*q+0].x = fmaf(v.x, w4.x, acc[4*q+0].x);
                        acc[4*q+0].y = fmaf(v.y, w4.x, acc[4*q+0].y);
                        acc[4*q+1].x = fmaf(v.x, w4.y, acc[4*q+1].x);
                        acc[4*q+1].y = fmaf(v.y, w4.y, acc[4*q+1].y);
                        acc[4*q+2].x = fmaf(v.x, w4.z, acc[4*q+2].x);
                        acc[4*q+2].y = fmaf(v.y, w4.z, acc[4*q+2].y);
                        acc[4*q+3].x = fmaf(v.x, w4.w, acc[4*q+3].x);
                        acc[4*q+3].y = fmaf(v.y, w4.w, acc[4*q+3].y);
                    }
                }
            }
        }
        #pragma unroll
        for (int ot = 0; ot < OT; ot++) {
            su[ot][2 * tp]     = acc[ot].x;
            su[ot][2 * tp + 1] = acc[ot].y;
        }
    }
    __syncthreads();

    // ---- spike phase: one thread per output channel, sequential over t ----
    if (tid < OT) {
        float rk[10]; load_refk(rk);
        float buf[10];
        #pragma unroll
        for (int j = 0; j < 10; j++) buf[j] = 0.f;
        #pragma unroll 4
        for (int t = 0; t < T_LEN; t++)
            su[tid][t] = spike_step(su[tid][t], buf, rk);
    }
    __syncthreads();

    // ---- coalesced spike store ----
    for (int i = tid; i < OT * (T_LEN / 2); i += 128) {
        const int ot = i / (T_LEN / 2);
        const int tp = i % (T_LEN / 2);
        const size_t ob =
            ((size_t)(((b * O + o0 + ot) * HOUT + y) * WOUT + x)) * T_LEN + 2 * tp;
        float2 v = make_float2(su[ot][2 * tp], su[ot][2 * tp + 1]);
        *reinterpret_cast<float2*>(&out[ob]) = v;
    }
}

// ---------------------------------------------------------------------------
// Fused sum-pool(2x2, x11) + spike.
// 128 output neurons per block; 32-step time tiles staged through smem so
// gathers and scatters are coalesced (row stride is T=300).
// Pool sums are exact: inputs are 0/1 spikes, sum <= 4, *11 exact.
// ---------------------------------------------------------------------------
template<int HI, int WI>
__global__ __launch_bounds__(128)
void pool_spike_kernel(const float* __restrict__ in, float* __restrict__ out,
                       int nNeurons)
{
    constexpr int HO = HI / 2, WO = WI / 2;
    __shared__ float tile[128][33];
    const int tid   = threadIdx.x;
    const int nbase = blockIdx.x * 128;

    float rk[10]; load_refk(rk);
    float buf[10];
    #pragma unroll
    for (int j = 0; j < 10; j++) buf[j] = 0.f;

    for (int t0 = 0; t0 < T_LEN; t0 += 32) {
        const int cnt = min(32, T_LEN - t0);

        #pragma unroll 1
        for (int k = 0; k < 32; k++) {       // coalesced gather + pool
            const int i  = k * 128 + tid;
            const int n  = i >> 5;
            const int tt = i & 31;
            const int id = nbase + n;
            if (tt < cnt && id < nNeurons) {
                const int xo = id % WO;
                const int yo = (id / WO) % HO;
                const int bc = id / (WO * HO);
                const size_t base =
                    ((size_t)((bc * HI + 2 * yo) * WI + 2 * xo)) * T_LEN + t0 + tt;
                const float s = ((in[base] + in[base + T_LEN])
                                 + in[base + (size_t)WI * T_LEN])
                                 + in[base + (size_t)WI * T_LEN + T_LEN];
                tile[n][tt] = 11.0f * s;     // 1.1 * theta
            }
        }
        __syncthreads();

        if (nbase + tid < nNeurons) {
            #pragma unroll
            for (int s = 0; s < 32; s++)
                if (s < cnt)
                    tile[tid][s] = spike_step(tile[tid][s], buf, rk);
        }
        __syncthreads();

        #pragma unroll 1
        for (int k = 0; k < 32; k++) {       // coalesced scatter
            const int i  = k * 128 + tid;
            const int n  = i >> 5;
            const int tt = i & 31;
            if (tt < cnt && nbase + n < nNeurons)
                out[(size_t)(nbase + n) * T_LEN + t0 + tt] = tile[n][tt];
        }
        __syncthreads();
    }
}

// ---------------------------------------------------------------------------
// Fused dense(4096 -> 10) + final spike.
// Block = (o, b); threads over t (coalesced s5 reads, broadcast weights);
// then thread 0 runs the 300-step recurrence in smem and writes out.
// ---------------------------------------------------------------------------
__global__ __launch_bounds__(320)
void fc_spike_kernel(const float* __restrict__ s5, const float* __restrict__ wfc,
                     float* __restrict__ out)
{
    __shared__ float su[T_LEN];
    const int tid = threadIdx.x;
    const int o = blockIdx.x;
    const int b = blockIdx.y;

    if (tid < T_LEN) {
        const float* ip = s5 + (size_t)b * 4096 * T_LEN + tid;
        const float* wp = wfc + (size_t)o * 4096;
        float acc = 0.f;
        #pragma unroll 8
        for (int i = 0; i < 4096; i++)
            acc = fmaf(__ldg(&ip[(size_t)i * T_LEN]), __ldg(&wp[i]), acc);
        su[tid] = acc;
    }
    __syncthreads();

    if (tid == 0) {
        float rk[10]; load_refk(rk);
        float buf[10];
        #pragma unroll
        for (int j = 0; j < 10; j++) buf[j] = 0.f;
        float* op = out + (size_t)(b * 10 + o) * T_LEN;
        for (int t = 0; t < T_LEN; t++)
            op[t] = spike_step(su[t], buf, rk);
    }
}

// ---------------------------------------------------------------------------
extern "C" void kernel_launch(void* const* d_in, const int* in_sizes, int n_in,
                              void* d_out, int out_size)
{
    const float* x   = (const float*)d_in[0];   // [8,2,34,34,300]
    const float* w1  = (const float*)d_in[1];   // [16,2,5,5]
    const float* w2  = (const float*)d_in[2];   // [32,16,3,3]
    const float* w3  = (const float*)d_in[3];   // [64,32,3,3]
    const float* wfc = (const float*)d_in[4];   // [10,64,8,8]
    float* out = (float*)d_out;                 // [8,10,1,1,300]

    float *s1, *s2, *s3, *s4, *s5;
    cudaGetSymbolAddress((void**)&s1, g_s1);
    cudaGetSymbolAddress((void**)&s2, g_s2);
    cudaGetSymbolAddress((void**)&s3, g_s3);
    cudaGetSymbolAddress((void**)&s4, g_s4);
    cudaGetSymbolAddress((void**)&s5, g_s5);

    // L1: conv 2->16 5x5 pad1 (34x34 -> 32x32) + spike
    conv_spike_kernel<2, 16, 5, 1, 34, 34, 32, 32, 16>
        <<<dim3(32 * 32, BATCH, 1), 128>>>(x, w1, s1);
    // pool 32->16 + spike
    pool_spike_kernel<32, 32>
        <<<(BATCH * 16 * 16 * 16 + 127) / 128, 128>>>(s1, s2, BATCH * 16 * 16 * 16);
    // L2: conv 16->32 3x3 pad1 (16x16) + spike
    conv_spike_kernel<16, 32, 3, 1, 16, 16, 16, 16, 16>
        <<<dim3(16 * 16, BATCH, 2), 128>>>(s2, w2, s3);
    // pool 16->8 + spike
    pool_spike_kernel<16, 16>
        <<<(BATCH * 32 * 8 * 8 + 127) / 128, 128>>>(s3, s4, BATCH * 32 * 8 * 8);
    // L3: conv 32->64 3x3 pad1 (8x8) + spike
    conv_spike_kernel<32, 64, 3, 1, 8, 8, 8, 8, 16>
        <<<dim3(8 * 8, BATCH, 4), 128>>>(s4, w3, s5);
    // dense 4096->10 + final spike
    fc_spike_kernel<<<dim3(10, BATCH), 320>>>(s5, wfc, out);
}

// round 7
// speedup vs baseline: 1.5828x; 1.5828x over previous
#include <cuda_runtime.h>
#include <math.h>

// ---------------------------------------------------------------------------
// SLAYER N-MNIST SNN forward, fused pipeline (6 launches):
//   conv1+spike -> pool+spike -> conv2+spike -> pool+spike -> conv3+spike
//   -> fc+spike(out)
// Layout everywhere: [B, C, H, W, T], T=300 innermost (matches reference).
// Intermediates hold SPIKES (0/1 floats); membrane potentials stay in smem.
// INVARIANT: conv accumulation order (c outer, dy, dx, sequential fmaf)
// bit-matches the reference (R3 rel_err == 0.0). Do not reorder.
// ---------------------------------------------------------------------------

#define T_LEN   300
#define BATCH   8
#define THETA   10.0f

__device__ float g_s1[BATCH * 16 * 32 * 32 * T_LEN];
__device__ float g_s2[BATCH * 16 * 16 * 16 * T_LEN];
__device__ float g_s3[BATCH * 32 * 16 * 16 * T_LEN];
__device__ float g_s4[BATCH * 32 *  8 *  8 * T_LEN];
__device__ float g_s5[BATCH * 64 *  8 *  8 * T_LEN];

// Refractory taps REF_KERNEL[1..10] = -20 * j * exp(1 - j), double->f32.
__device__ __forceinline__ void load_refk(float rk[10]) {
    #pragma unroll
    for (int j = 0; j < 10; j++)
        rk[j] = (float)(-20.0 * (double)(j + 1) * exp(1.0 - (double)(j + 1)));
}

// One spike-recurrence step; matches jax.lax.scan step exactly (ev in {0,1}
// makes ev*rk exact, so fmaf == the reference's single-rounded add).
__device__ __forceinline__ float spike_step(float u_raw, float buf[10],
                                            const float rk[10]) {
    const float um = u_raw + buf[0];
    const float ev = (um >= THETA) ? 1.0f : 0.0f;
    #pragma unroll
    for (int j = 0; j < 9; j++)
        buf[j] = fmaf(ev, rk[j], buf[j + 1]);
    buf[9] = ev * rk[9];
    return ev;
}

// ---------------------------------------------------------------------------
// Fused conv + spike.
// Block = one (b, y, x) for OT output channels; 160 threads, thread tid
// owns time-pair tp = tid (150 active -> no inter-warp imbalance).
// Membrane potential lives in smem su[OT][301]; spikes stored coalesced.
// ---------------------------------------------------------------------------
template<int C, int O, int K, int PAD, int HIN, int WIN, int HOUT, int WOUT, int OT>
__global__ __launch_bounds__(160)
void conv_spike_kernel(const float* __restrict__ in, const float* __restrict__ wt,
                       float* __restrict__ out)
{
    constexpr int KK = K * K;
    constexpr int SUP = 301;
    __shared__ float sw[C * KK * OT];
    __shared__ float su[OT][SUP];

    const int tid = threadIdx.x;
    const int o0  = blockIdx.z * OT;

    // Stage weights transposed: sw[j*OT + ot] = wt[(o0+ot)*C*KK + j]
    for (int i = tid; i < C * KK * OT; i += 160) {
        int ot = i % OT;
        int j  = i / OT;
        sw[j * OT + ot] = wt[(size_t)(o0 + ot) * C * KK + j];
    }
    __syncthreads();

    const int y = blockIdx.x / WOUT;
    const int x = blockIdx.x % WOUT;
    const int b = blockIdx.y;

    // ---- conv phase: one float2 time-pair per thread ----
    if (tid < T_LEN / 2) {
        const int tp = tid;
        float2 acc[OT];
        #pragma unroll
        for (int ot = 0; ot < OT; ot++) { acc[ot].x = 0.f; acc[ot].y = 0.f; }

        #pragma unroll 1
        for (int c = 0; c < C; c++) {
            #pragma unroll
            for (int dy = 0; dy < K; dy++) {
                const int iy = y + dy - PAD;
                if (iy < 0 || iy >= HIN) continue;
                #pragma unroll
                for (int dx = 0; dx < K; dx++) {
                    const int ix = x + dx - PAD;
                    if (ix < 0 || ix >= WIN) continue;
                    const size_t ib =
                        ((size_t)(((b * C + c) * HIN + iy) * WIN + ix)) * T_LEN + 2 * tp;
                    const float2 v = *reinterpret_cast<const float2*>(&in[ib]);
                    const float4* wrow =
                        reinterpret_cast<const float4*>(&sw[(c * KK + dy * K + dx) * OT]);
                    #pragma unroll
                    for (int q = 0; q < OT / 4; q++) {
                        const float4 w4 = wrow[q];
                        acc[4*q+0].x = fmaf(v.x, w4.x, acc[4*q+0].x);
                        acc[4*q+0].y = fmaf(v.y, w4.x, acc[4*q+0].y);
                        acc[4*q+1].x = fmaf(v.x, w4.y, acc[4*q+1].x);
                        acc[4*q+1].y = fmaf(v.y, w4.y, acc[4*q+1].y);
                        acc[4*q+2].x = fmaf(v.x, w4.z, acc[4*q+2].x);
                        acc[4*q+2].y = fmaf(v.y, w4.z, acc[4*q+2].y);
                        acc[4*q+3].x = fmaf(v.x, w4.w, acc[4*q+3].x);
                        acc[4*q+3].y = fmaf(v.y, w4.w, acc[4*q+3].y);
                    }
                }
            }
        }
        #pragma unroll
        for (int ot = 0; ot < OT; ot++) {
            su[ot][2 * tp]     = acc[ot].x;
            su[ot][2 * tp + 1] = acc[ot].y;
        }
    }
    __syncthreads();

    // ---- spike phase: one thread per output channel, sequential over t ----
    if (tid < OT) {
        float rk[10]; load_refk(rk);
        float buf[10];
        #pragma unroll
        for (int j = 0; j < 10; j++) buf[j] = 0.f;
        #pragma unroll 4
        for (int t = 0; t < T_LEN; t++)
            su[tid][t] = spike_step(su[tid][t], buf, rk);
    }
    __syncthreads();

    // ---- coalesced spike store ----
    for (int i = tid; i < OT * (T_LEN / 2); i += 160) {
        const int ot = i / (T_LEN / 2);
        const int tp = i % (T_LEN / 2);
        const size_t ob =
            ((size_t)(((b * O + o0 + ot) * HOUT + y) * WOUT + x)) * T_LEN + 2 * tp;
        float2 v = make_float2(su[ot][2 * tp], su[ot][2 * tp + 1]);
        *reinterpret_cast<float2*>(&out[ob]) = v;
    }
}

// ---------------------------------------------------------------------------
// Fused sum-pool(2x2, x11) + spike — latency-optimized.
// Block = 32 neurons, 128 threads, smem su[32][301] (38.5 KB). Single
// full-T float4 gather (deep MLP, coalesced), one recurrence pass (warp 0,
// stride 301 -> conflict-free), float4 scatter.
// Pool sums exact: inputs are 0/1 spikes, sum <= 4, *11 exact in fp32.
// ---------------------------------------------------------------------------
template<int HI, int WI>
__global__ __launch_bounds__(128)
void pool_spike_kernel(const float* __restrict__ in, float* __restrict__ out,
                       int nNeurons)
{
    constexpr int HO = HI / 2, WO = WI / 2;
    constexpr int NQ = T_LEN / 4;            // 75 float4 per row
    __shared__ float su[32][301];
    const int tid   = threadIdx.x;
    const int nbase = blockIdx.x * 32;

    // ---- gather + pool: all 300 steps in one phase ----
    #pragma unroll 2
    for (int i = tid; i < 32 * NQ; i += 128) {
        const int n  = i / NQ;
        const int q  = i % NQ;
        const int id = nbase + n;
        const int xo = id % WO;
        const int yo = (id / WO) % HO;
        const int bc = id / (WO * HO);
        const size_t base =
            ((size_t)((bc * HI + 2 * yo) * WI + 2 * xo)) * T_LEN + 4 * q;
        const float4 a = *reinterpret_cast<const float4*>(in + base);
        const float4 b = *reinterpret_cast<const float4*>(in + base + T_LEN);
        const float4 c = *reinterpret_cast<const float4*>(in + base + (size_t)WI * T_LEN);
        const float4 d = *reinterpret_cast<const float4*>(in + base + (size_t)WI * T_LEN + T_LEN);
        su[n][4 * q + 0] = 11.0f * (((a.x + b.x) + c.x) + d.x);
        su[n][4 * q + 1] = 11.0f * (((a.y + b.y) + c.y) + d.y);
        su[n][4 * q + 2] = 11.0f * (((a.z + b.z) + c.z) + d.z);
        su[n][4 * q + 3] = 11.0f * (((a.w + b.w) + c.w) + d.w);
    }
    __syncthreads();

    // ---- recurrence: warp 0, one neuron per lane ----
    if (tid < 32) {
        float rk[10]; load_refk(rk);
        float buf[10];
        #pragma unroll
        for (int j = 0; j < 10; j++) buf[j] = 0.f;
        #pragma unroll 4
        for (int t = 0; t < T_LEN; t++)
            su[tid][t] = spike_step(su[tid][t], buf, rk);
    }
    __syncthreads();

    // ---- float4 coalesced scatter ----
    #pragma unroll 2
    for (int i = tid; i < 32 * NQ; i += 128) {
        const int n = i / NQ;
        const int q = i % NQ;
        float4 v = make_float4(su[n][4*q+0], su[n][4*q+1],
                               su[n][4*q+2], su[n][4*q+3]);
        *reinterpret_cast<float4*>(out + (size_t)(nbase + n) * T_LEN + 4 * q) = v;
    }
}

// ---------------------------------------------------------------------------
// Fused dense(4096 -> 10) + final spike.
// ---------------------------------------------------------------------------
__global__ __launch_bounds__(320)
void fc_spike_kernel(const float* __restrict__ s5, const float* __restrict__ wfc,
                     float* __restrict__ out)
{
    __shared__ float su[T_LEN];
    const int tid = threadIdx.x;
    const int o = blockIdx.x;
    const int b = blockIdx.y;

    if (tid < T_LEN) {
        const float* ip = s5 + (size_t)b * 4096 * T_LEN + tid;
        const float* wp = wfc + (size_t)o * 4096;
        float acc = 0.f;
        #pragma unroll 16
        for (int i = 0; i < 4096; i++)
            acc = fmaf(__ldg(&ip[(size_t)i * T_LEN]), __ldg(&wp[i]), acc);
        su[tid] = acc;
    }
    __syncthreads();

    if (tid == 0) {
        float rk[10]; load_refk(rk);
        float buf[10];
        #pragma unroll
        for (int j = 0; j < 10; j++) buf[j] = 0.f;
        float* op = out + (size_t)(b * 10 + o) * T_LEN;
        for (int t = 0; t < T_LEN; t++)
            op[t] = spike_step(su[t], buf, rk);
    }
}

// ---------------------------------------------------------------------------
extern "C" void kernel_launch(void* const* d_in, const int* in_sizes, int n_in,
                              void* d_out, int out_size)
{
    const float* x   = (const float*)d_in[0];   // [8,2,34,34,300]
    const float* w1  = (const float*)d_in[1];   // [16,2,5,5]
    const float* w2  = (const float*)d_in[2];   // [32,16,3,3]
    const float* w3  = (const float*)d_in[3];   // [64,32,3,3]
    const float* wfc = (const float*)d_in[4];   // [10,64,8,8]
    float* out = (float*)d_out;                 // [8,10,1,1,300]

    float *s1, *s2, *s3, *s4, *s5;
    cudaGetSymbolAddress((void**)&s1, g_s1);
    cudaGetSymbolAddress((void**)&s2, g_s2);
    cudaGetSymbolAddress((void**)&s3, g_s3);
    cudaGetSymbolAddress((void**)&s4, g_s4);
    cudaGetSymbolAddress((void**)&s5, g_s5);

    // L1: conv 2->16 5x5 pad1 (34x34 -> 32x32) + spike
    conv_spike_kernel<2, 16, 5, 1, 34, 34, 32, 32, 16>
        <<<dim3(32 * 32, BATCH, 1), 160>>>(x, w1, s1);
    // pool 32->16 + spike (32768 neurons -> 1024 blocks)
    pool_spike_kernel<32, 32>
        <<<(BATCH * 16 * 16 * 16) / 32, 128>>>(s1, s2, BATCH * 16 * 16 * 16);
    // L2: conv 16->32 3x3 pad1 (16x16) + spike
    conv_spike_kernel<16, 32, 3, 1, 16, 16, 16, 16, 16>
        <<<dim3(16 * 16, BATCH, 2), 160>>>(s2, w2, s3);
    // pool 16->8 + spike (16384 neurons -> 512 blocks)
    pool_spike_kernel<16, 16>
        <<<(BATCH * 32 * 8 * 8) / 32, 128>>>(s3, s4, BATCH * 32 * 8 * 8);
    // L3: conv 32->64 3x3 pad1 (8x8) + spike
    conv_spike_kernel<32, 64, 3, 1, 8, 8, 8, 8, 16>
        <<<dim3(8 * 8, BATCH, 4), 160>>>(s4, w3, s5);
    // dense 4096->10 + final spike
    fc_spike_kernel<<<dim3(10, BATCH), 320>>>(s5, wfc, out);
}